// round 3
// baseline (speedup 1.0000x reference)
#include <cuda_runtime.h>
#include <cstdint>

#define NB 256   // batch
#define NN 256   // target particles
#define NM 256   // reco particles
#define ND 4     // feature dim

// Scratch: [0..NB): eucl_non_zero, [NB..2*NB): eucl_zero
__device__ float g_part[2 * NB];
__device__ int   g_count = 0;

static __device__ __forceinline__ uint64_t dup2(float v) {
    uint64_t r; asm("mov.b64 %0, {%1, %1};" : "=l"(r) : "f"(v)); return r;
}
static __device__ __forceinline__ uint64_t ffma2(uint64_t a, uint64_t b, uint64_t c) {
    uint64_t d; asm("fma.rn.f32x2 %0, %1, %2, %3;" : "=l"(d) : "l"(a), "l"(b), "l"(c)); return d;
}
static __device__ __forceinline__ void unpk(uint64_t v, float &lo, float &hi) {
    asm("mov.b64 {%0, %1}, %2;" : "=f"(lo), "=f"(hi) : "l"(v));
}

__global__ __launch_bounds__(256) void chamfer_kernel(
    const float* __restrict__ target,
    const float* __restrict__ reco,
    const int*   __restrict__ in_pid,
    const int*   __restrict__ out_pid,
    float*       __restrict__ out)
{
    // Pair-interleaved layouts for f32x2: per pair p (points 2p, 2p+1)
    //   spA[p] = { (-2x0,-2x1), (-2y0,-2y1) }  (two u64 lanes)
    //   spB[p] = { (-2z0,-2z1), (-2w0,-2w1) }
    //   spc[p] = ( c0, c1 )  where c = ||pt||^2 + pen (pen = 0 or 1e20)
    __shared__ ulonglong2 sxA[NN/2], sxB[NN/2];
    __shared__ ulonglong2 syA[NM/2], syB[NM/2];
    __shared__ uint64_t   sxc[NN/2], syc[NM/2];
    __shared__ float4     red[256];
    __shared__ int        s_last;

    const int b = blockIdx.x;
    const int t = threadIdx.x;
    const int p = t >> 1, l = t & 1;

    const float4* tg = (const float4*)(target + (size_t)b * NN * ND);
    const float4* rc = (const float4*)(reco   + (size_t)b * NM * ND);
    float4 xt = tg[t];
    float4 yt = rc[t];

    const int mx = (in_pid[b * NN + t] != 0);
    const int my = (out_pid[b * NM + t] != 0);

    const float n2x = xt.x*xt.x + xt.y*xt.y + xt.z*xt.z + xt.w*xt.w;
    const float n2y = yt.x*yt.x + yt.y*yt.y + yt.z*yt.z + yt.w*yt.w;

    // scatter into pair-interleaved shared (one-time setup; minor conflicts OK)
    {
        float* a = (float*)sxA; float* c = (float*)sxB;
        a[p*4 + l]     = -2.0f * xt.x;
        a[p*4 + 2 + l] = -2.0f * xt.y;
        c[p*4 + l]     = -2.0f * xt.z;
        c[p*4 + 2 + l] = -2.0f * xt.w;
        ((float*)sxc)[t] = n2x + (mx ? 0.0f : 1e20f);

        float* ay = (float*)syA; float* cy = (float*)syB;
        ay[p*4 + l]     = -2.0f * yt.x;
        ay[p*4 + 2 + l] = -2.0f * yt.y;
        cy[p*4 + l]     = -2.0f * yt.z;
        cy[p*4 + 2 + l] = -2.0f * yt.w;
        ((float*)syc)[t] = n2y + (my ? 0.0f : 1e20f);
    }

    const int nx = __syncthreads_count(mx);
    const int ny = __syncthreads_count(my);

    // ---- pass 1: min over m of (||y||^2 + pen - 2 x_t . y) ----
    const uint64_t xx = dup2(xt.x), xy = dup2(xt.y), xz = dup2(xt.z), xw = dup2(xt.w);
    float dlo = 3.0e38f, dhi = 3.0e38f;
    #pragma unroll 8
    for (int m = 0; m < NM/2; ++m) {
        ulonglong2 A = syA[m];      // broadcast LDS.128
        ulonglong2 B = syB[m];      // broadcast LDS.128
        uint64_t s = syc[m];        // broadcast LDS.64
        s = ffma2(A.x, xx, s);
        s = ffma2(A.y, xy, s);
        s = ffma2(B.x, xz, s);
        s = ffma2(B.y, xw, s);
        float lo, hi; unpk(s, lo, hi);
        dlo = fminf(dlo, lo);
        dhi = fminf(dhi, hi);
    }
    float d2_xy = fmaxf(fminf(dlo, dhi) + n2x, 0.0f);
    float c_sum_xy = mx ? sqrtf(d2_xy) : 0.0f;

    // ---- pass 2: min over n of (||x||^2 + pen - 2 x . y_t) ----
    const uint64_t yx = dup2(yt.x), yy = dup2(yt.y), yz = dup2(yt.z), yw = dup2(yt.w);
    dlo = 3.0e38f; dhi = 3.0e38f;
    #pragma unroll 8
    for (int n = 0; n < NN/2; ++n) {
        ulonglong2 A = sxA[n];
        ulonglong2 B = sxB[n];
        uint64_t s = sxc[n];
        s = ffma2(A.x, yx, s);
        s = ffma2(A.y, yy, s);
        s = ffma2(B.x, yz, s);
        s = ffma2(B.y, yw, s);
        float lo, hi; unpk(s, lo, hi);
        dlo = fminf(dlo, lo);
        dhi = fminf(dhi, hi);
    }
    float d2_yx = fmaxf(fminf(dlo, dhi) + n2y, 0.0f);
    float c_sum_yx = my ? sqrtf(d2_yx) : 0.0f;

    // edge-case norms
    float c_nrmx  = mx ? sqrtf(n2x) : 0.0f;   // sum over mask_x of ||x||
    float c_nrmy0 = my ? 0.0f : sqrtf(n2y);   // sum over ~mask_y of ||y||

    // ---- block tree reduction of the 4 sums ----
    red[t] = make_float4(c_sum_xy, c_sum_yx, c_nrmx, c_nrmy0);
    __syncthreads();
    #pragma unroll
    for (int s = 128; s > 0; s >>= 1) {
        if (t < s) {
            float4 a = red[t], c = red[t + s];
            a.x += c.x; a.y += c.y; a.z += c.z; a.w += c.w;
            red[t] = a;
        }
        __syncthreads();
    }

    if (t == 0) {
        float4 r = red[0];
        float n_in  = (float)max(1, nx);
        float n_out = (float)max(1, ny);
        float normal = 0.5f * (r.x / n_out + r.y / n_in);
        float eucl_non_zero;
        if (ny == 0)       eucl_non_zero = r.z / n_in;
        else if (nx == 0)  eucl_non_zero = 0.0f;
        else               eucl_non_zero = normal;
        float n_zero = (float)max(1, NM - ny);
        g_part[b]      = eucl_non_zero;
        g_part[NB + b] = r.w / n_zero;

        __threadfence();
        int old = atomicAdd(&g_count, 1);
        s_last = (old == NB - 1);
    }
    __syncthreads();

    // ---- last block: fused finalize (deterministic fixed-order tree) ----
    if (s_last) {
        if (t == 0) g_count = 0;   // self-reset for graph replay
        // L1 is not coherent across SMs: read through L2
        float v0 = __ldcg(&g_part[t]);
        float v1 = __ldcg(&g_part[NB + t]);
        red[t] = make_float4(v0, v1, 0.0f, 0.0f);
        __syncthreads();
        #pragma unroll
        for (int s = 128; s > 0; s >>= 1) {
            if (t < s) {
                float4 a = red[t], c = red[t + s];
                a.x += c.x; a.y += c.y;
                red[t] = a;
            }
            __syncthreads();
        }
        if (t == 0) {
            out[0] = red[0].x * (1.0f / NB);
            out[1] = red[0].y * (1.0f / NB);
        }
    }
}

extern "C" void kernel_launch(void* const* d_in, const int* in_sizes, int n_in,
                              void* d_out, int out_size)
{
    const float* target  = (const float*)d_in[0];
    const float* reco    = (const float*)d_in[1];
    const int*   in_pid  = (const int*)d_in[2];
    const int*   out_pid = (const int*)d_in[3];
    float* out = (float*)d_out;

    chamfer_kernel<<<NB, 256>>>(target, reco, in_pid, out_pid, out);
}

// round 4
// speedup vs baseline: 1.2937x; 1.2937x over previous
#include <cuda_runtime.h>
#include <cstdint>

#define NB 256   // batch
#define NPTS 256 // points per side (N == M)
#define ND 4

// per-batch partials: [0]=sum_xy [1]=sum_nrmx [2]=nx [3]=sum_yx [4]=sum_nrmy0 [5]=ny
__device__ float g_sc[6 * NB];
__device__ int   g_count = 0;

static __device__ __forceinline__ uint64_t dup2(float v) {
    uint64_t r; asm("mov.b64 %0, {%1, %1};" : "=l"(r) : "f"(v)); return r;
}
static __device__ __forceinline__ uint64_t ffma2(uint64_t a, uint64_t b, uint64_t c) {
    uint64_t d; asm("fma.rn.f32x2 %0, %1, %2, %3;" : "=l"(d) : "l"(a), "l"(b), "l"(c)); return d;
}
static __device__ __forceinline__ void unpk(uint64_t v, float &lo, float &hi) {
    asm("mov.b64 {%0, %1}, %2;" : "=f"(lo), "=f"(hi) : "l"(v));
}

__global__ __launch_bounds__(128, 8) void chamfer_kernel(
    const float* __restrict__ target,
    const float* __restrict__ reco,
    const int*   __restrict__ in_pid,
    const int*   __restrict__ out_pid,
    float*       __restrict__ out)
{
    // Pair-interleaved tile for f32x2: pair p covers points 2p, 2p+1:
    //  sA[p] = { (-2x_e0,-2x_e1) packed comp0, comp1 }, sB comp2, comp3
    //  sc[p] = ( ||pt0||^2+pen0 , ||pt1||^2+pen1 )
    __shared__ ulonglong2 sA[NPTS/2], sB[NPTS/2];
    __shared__ uint64_t   sc[NPTS/2];
    __shared__ float4     red[128];
    __shared__ int        s_last;

    const int bid   = blockIdx.x;
    const int b     = bid >> 1;
    const int phase = bid & 1;        // 0: rows=target, tile=reco ; 1: rows=reco, tile=target
    const int t     = threadIdx.x;

    const float* tileSrc = phase == 0 ? reco    : target;
    const int*   tilePid = phase == 0 ? out_pid : in_pid;
    const float* rowSrc  = phase == 0 ? target  : reco;
    const int*   rowPid  = phase == 0 ? in_pid  : out_pid;

    const float4* tile4 = (const float4*)(tileSrc + (size_t)b * NPTS * ND);
    const float4* row4  = (const float4*)(rowSrc  + (size_t)b * NPTS * ND);
    const int*    tpid  = tilePid + b * NPTS;
    const int*    rpid  = rowPid  + b * NPTS;

    // ---- build shared tile (each thread handles 2 tile points) ----
    #pragma unroll
    for (int k = 0; k < 2; ++k) {
        int i = t + k * 128;
        float4 v = tile4[i];
        int pid  = tpid[i];
        float n2 = v.x*v.x + v.y*v.y + v.z*v.z + v.w*v.w;
        int pair = i >> 1, lane = i & 1;
        ((float*)sA)[pair*4 + lane]     = -2.0f * v.x;
        ((float*)sA)[pair*4 + 2 + lane] = -2.0f * v.y;
        ((float*)sB)[pair*4 + lane]     = -2.0f * v.z;
        ((float*)sB)[pair*4 + 2 + lane] = -2.0f * v.w;
        ((float*)sc)[i] = n2 + (pid != 0 ? 0.0f : 1e20f);
    }

    // ---- own 2 rows ----
    float4 v0 = row4[t];
    float4 v1 = row4[t + 128];
    const int m0 = (rpid[t] != 0);
    const int m1 = (rpid[t + 128] != 0);
    const float n20 = v0.x*v0.x + v0.y*v0.y + v0.z*v0.z + v0.w*v0.w;
    const float n21 = v1.x*v1.x + v1.y*v1.y + v1.z*v1.z + v1.w*v1.w;

    const uint64_t r0x = dup2(v0.x), r0y = dup2(v0.y), r0z = dup2(v0.z), r0w = dup2(v0.w);
    const uint64_t r1x = dup2(v1.x), r1y = dup2(v1.y), r1z = dup2(v1.z), r1w = dup2(v1.w);

    __syncthreads();

    // ---- main loop: min over tile of (||p||^2 + pen - 2 row . p), 2 rows x 2 pts/iter ----
    float d0lo = 3.0e38f, d0hi = 3.0e38f, d1lo = 3.0e38f, d1hi = 3.0e38f;
    #pragma unroll 8
    for (int m = 0; m < NPTS/2; ++m) {
        ulonglong2 A = sA[m];           // broadcast LDS.128
        ulonglong2 B = sB[m];           // broadcast LDS.128
        uint64_t   c = sc[m];           // broadcast LDS.64
        uint64_t s0 = ffma2(A.x, r0x, c);
        uint64_t s1 = ffma2(A.x, r1x, c);
        s0 = ffma2(A.y, r0y, s0);
        s1 = ffma2(A.y, r1y, s1);
        s0 = ffma2(B.x, r0z, s0);
        s1 = ffma2(B.x, r1z, s1);
        s0 = ffma2(B.y, r0w, s0);
        s1 = ffma2(B.y, r1w, s1);
        float lo, hi;
        unpk(s0, lo, hi);
        d0lo = fminf(d0lo, lo); d0hi = fminf(d0hi, hi);
        unpk(s1, lo, hi);
        d1lo = fminf(d1lo, lo); d1hi = fminf(d1hi, hi);
    }
    float d20 = fmaxf(fminf(d0lo, d0hi) + n20, 0.0f);
    float d21 = fmaxf(fminf(d1lo, d1hi) + n21, 0.0f);

    float sum_min = (m0 ? sqrtf(d20) : 0.0f) + (m1 ? sqrtf(d21) : 0.0f);
    float sum_nrm;
    if (phase == 0)   // sum ||x|| over mask_x
        sum_nrm = (m0 ? sqrtf(n20) : 0.0f) + (m1 ? sqrtf(n21) : 0.0f);
    else              // sum ||y|| over ~mask_y
        sum_nrm = (m0 ? 0.0f : sqrtf(n20)) + (m1 ? 0.0f : sqrtf(n21));
    float cnt = (float)(m0 + m1);     // nx (phase 0) or ny (phase 1)

    // ---- block tree reduction ----
    red[t] = make_float4(sum_min, sum_nrm, cnt, 0.0f);
    __syncthreads();
    #pragma unroll
    for (int s = 64; s > 0; s >>= 1) {
        if (t < s) {
            float4 a = red[t], c = red[t + s];
            a.x += c.x; a.y += c.y; a.z += c.z;
            red[t] = a;
        }
        __syncthreads();
    }

    if (t == 0) {
        float4 r = red[0];
        g_sc[(phase*3 + 0) * NB + b] = r.x;
        g_sc[(phase*3 + 1) * NB + b] = r.y;
        g_sc[(phase*3 + 2) * NB + b] = r.z;
        __threadfence();
        int old = atomicAdd(&g_count, 1);
        s_last = (old == 2*NB - 1);
    }
    __syncthreads();

    // ---- last block: fused finalize ----
    if (s_last) {
        if (t == 0) g_count = 0;      // reset for graph replay
        float acc0 = 0.0f, acc1 = 0.0f;
        #pragma unroll
        for (int k = 0; k < 2; ++k) {
            int bb = t + k * 128;
            float sum_xy    = __ldcg(&g_sc[0*NB + bb]);
            float sum_nrmx  = __ldcg(&g_sc[1*NB + bb]);
            float fnx       = __ldcg(&g_sc[2*NB + bb]);
            float sum_yx    = __ldcg(&g_sc[3*NB + bb]);
            float sum_nrmy0 = __ldcg(&g_sc[4*NB + bb]);
            float fny       = __ldcg(&g_sc[5*NB + bb]);
            float n_in  = fmaxf(1.0f, fnx);
            float n_out = fmaxf(1.0f, fny);
            float normal = 0.5f * (sum_xy / n_out + sum_yx / n_in);
            float e_nz = (fny == 0.0f) ? (sum_nrmx / n_in)
                       : ((fnx == 0.0f) ? 0.0f : normal);
            float e_z  = sum_nrmy0 / fmaxf(1.0f, (float)NPTS - fny);
            acc0 += e_nz;
            acc1 += e_z;
        }
        red[t] = make_float4(acc0, acc1, 0.0f, 0.0f);
        __syncthreads();
        #pragma unroll
        for (int s = 64; s > 0; s >>= 1) {
            if (t < s) {
                float4 a = red[t], c = red[t + s];
                a.x += c.x; a.y += c.y;
                red[t] = a;
            }
            __syncthreads();
        }
        if (t == 0) {
            out[0] = red[0].x * (1.0f / NB);
            out[1] = red[0].y * (1.0f / NB);
        }
    }
}

extern "C" void kernel_launch(void* const* d_in, const int* in_sizes, int n_in,
                              void* d_out, int out_size)
{
    const float* target  = (const float*)d_in[0];
    const float* reco    = (const float*)d_in[1];
    const int*   in_pid  = (const int*)d_in[2];
    const int*   out_pid = (const int*)d_in[3];
    float* out = (float*)d_out;

    chamfer_kernel<<<2 * NB, 128>>>(target, reco, in_pid, out_pid, out);
}